// round 1
// baseline (speedup 1.0000x reference)
#include <cuda_runtime.h>
#include <cstddef>

// ---------------------------------------------------------------------------
// SpikeNN LIF simulation.
//   inp: [B=64, N_IN=512, T=512] float (binary 0/1)
//   W:   [N=2048, N=2048] float, row i = incoming weights of neuron i
//   out: [B=64, N_OUT=256, T=512] float spikes of neurons 1792..2047
//
// Neurons 0..511 are irrelevant (their spike outputs are overwritten by the
// input every step and they are not part of the output), so we simulate only
// neurons 512..2047 (1536 "effective" neurons, local index i = global-512).
//
// Decomposition:
//   Phase 0: transpose W[512.., 0..512) -> Wt[512][1536] (k-major for GEMM)
//   Phase 1: Z[b,t,i] = sum_{j<512} W[512+i, j] * inp[b,j,t]   (big GEMM)
//   Phase 2: sequential LIF over T with sparse recurrent spike gather
// ---------------------------------------------------------------------------

#define KOEFF 0.9512294245007140f   // exp(-1/20), fp32
#define NEFF  1536
#define NIN   512
#define NTOT  2048
#define NB    64
#define NT    512
#define NOUT  256

// Scratch (allowed: __device__ globals, no cudaMalloc)
__device__ float g_Z[(size_t)NB * NT * NEFF];   // [b][t][i]  (192 MB)
__device__ float g_Wt[(size_t)NIN * NEFF];      // [k][i]     (3 MB)

// ---------------------------------------------------------------------------
// Phase 0: Wt[k][i] = W[(512+i)*2048 + k]
// ---------------------------------------------------------------------------
__global__ void transpose_w(const float* __restrict__ W) {
    int idx = blockIdx.x * 256 + threadIdx.x;
    if (idx < NIN * NEFF) {
        int k = idx / NEFF;
        int i = idx - k * NEFF;
        g_Wt[idx] = W[(size_t)(NIN + i) * NTOT + k];
    }
}

// ---------------------------------------------------------------------------
// Phase 1: SGEMM  C[m][n] = sum_k A[m][k] * Wt[k][n]
//   m = b*512 + t  (so A columns are contiguous in t -> coalesced loads)
//   A[m][k] = inp[b*512*512 + k*512 + t]
//   C -> g_Z[m*1536 + n]  (== [b][t][i])
// Tile: BM=BN=128, BK=16, 256 threads, 8x8 per thread (4+4 split columns/rows
// to keep vectorized smem reads conflict-light).
// ---------------------------------------------------------------------------
__global__ void __launch_bounds__(256, 2)
input_gemm(const float* __restrict__ inp) {
    __shared__ float As[16][132];   // [k][m], padded
    __shared__ float Bs[16][132];   // [k][n], padded

    const int m0    = blockIdx.y * 128;
    const int n0    = blockIdx.x * 128;
    const int b     = m0 >> 9;        // 128 | 512, so b constant per tile
    const int tbase = m0 & 511;

    const int tid = threadIdx.x;
    const int lk  = tid >> 5;         // 0..7
    const int lm  = (tid & 31) << 2;  // 0,4,...,124

    const float* Abase = inp + (size_t)b * (NIN * NT) + tbase + lm;
    const float* Bbase = g_Wt + n0 + lm;

    const int ty = tid >> 4;          // 0..15 -> rows
    const int tx = tid & 15;          // 0..15 -> cols

    float acc[8][8];
#pragma unroll
    for (int i = 0; i < 8; i++)
#pragma unroll
        for (int j = 0; j < 8; j++) acc[i][j] = 0.f;

    for (int k0 = 0; k0 < NIN; k0 += 16) {
#pragma unroll
        for (int l = 0; l < 2; l++) {
            int k = lk + l * 8;
            float4 va = *(const float4*)(Abase + (size_t)(k0 + k) * NT);
            *(float4*)&As[k][lm] = va;
            float4 vb = *(const float4*)(Bbase + (size_t)(k0 + k) * NEFF);
            *(float4*)&Bs[k][lm] = vb;
        }
        __syncthreads();

#pragma unroll
        for (int k = 0; k < 16; k++) {
            float a[8], bb[8];
            *(float4*)(a)      = *(const float4*)&As[k][ty * 4];
            *(float4*)(a + 4)  = *(const float4*)&As[k][64 + ty * 4];
            *(float4*)(bb)     = *(const float4*)&Bs[k][tx * 4];
            *(float4*)(bb + 4) = *(const float4*)&Bs[k][64 + tx * 4];
#pragma unroll
            for (int i = 0; i < 8; i++)
#pragma unroll
                for (int j = 0; j < 8; j++)
                    acc[i][j] += a[i] * bb[j];
        }
        __syncthreads();
    }

#pragma unroll
    for (int i = 0; i < 8; i++) {
        int gm = m0 + ((i < 4) ? (ty * 4 + i) : (64 + ty * 4 + i - 4));
        float* zr = g_Z + (size_t)gm * NEFF + n0;
        float4 v0 = make_float4(acc[i][0], acc[i][1], acc[i][2], acc[i][3]);
        float4 v1 = make_float4(acc[i][4], acc[i][5], acc[i][6], acc[i][7]);
        *(float4*)&zr[tx * 4]      = v0;
        *(float4*)&zr[64 + tx * 4] = v1;
    }
}

// ---------------------------------------------------------------------------
// Phase 2: sequential LIF. One block per batch, 512 threads, 3 neurons/thread.
// Per step:
//   state = state*KOEFF + Z[t] + rec(prev spikes)
//   if (refr > 0) state = 0
//   spike = state >= 1
//   refr -= 1; if (spike) refr = 2
//   if (state < -1) state = -1
// Recurrent term for the NEXT step is gathered from the spike list (binary,
// expected empty). Z[t+1] is prefetched to hide DRAM latency behind barriers.
// ---------------------------------------------------------------------------
__global__ void __launch_bounds__(512)
lif_kernel(const float* __restrict__ W, float* __restrict__ out) {
    __shared__ int cnt[2];
    __shared__ int list[2][NEFF];

    const int b   = blockIdx.x;
    const int tid = threadIdx.x;

    float state[3] = {0.f, 0.f, 0.f};
    float refr[3]  = {0.f, 0.f, 0.f};
    float rec[3]   = {0.f, 0.f, 0.f};

    if (tid < 2) cnt[tid] = 0;

    const float* Zb   = g_Z + (size_t)b * (NT * NEFF);
    float*       outb = out + (size_t)b * (NOUT * NT);

    // preload t = 0
    float zc[3], zn[3];
#pragma unroll
    for (int r = 0; r < 3; r++) zc[r] = Zb[tid + r * 512];

    __syncthreads();

    for (int t = 0; t < NT; t++) {
        const int cur = t & 1;

        // prefetch next step's drive early (overlaps compute + barriers)
        if (t < NT - 1) {
#pragma unroll
            for (int r = 0; r < 3; r++)
                zn[r] = Zb[(size_t)(t + 1) * NEFF + tid + r * 512];
        }

        float sp2 = 0.f;
#pragma unroll
        for (int r = 0; r < 3; r++) {
            float s = state[r] * KOEFF + zc[r] + rec[r];
            if (refr[r] > 0.f) s = 0.f;
            bool spike = (s >= 1.f);
            refr[r] -= 1.f;
            if (spike) refr[r] = 2.f;
            if (s < -1.f) s = -1.f;
            state[r] = s;
            if (r == 2) sp2 = spike ? 1.f : 0.f;
            if (spike) {
                int p = atomicAdd(&cnt[cur], 1);
                list[cur][p] = tid + r * 512;
            }
        }

        // output: local neurons 1280..1535 == tid+1024 for tid in [256,512)
        if (tid >= 256) outb[(size_t)(tid - 256) * NT + t] = sp2;

        __syncthreads();

        // recurrent gather for next step (expected n == 0)
        const int n = cnt[cur];
        rec[0] = rec[1] = rec[2] = 0.f;
        for (int a = 0; a < n; a++) {
            int j = list[cur][a];   // local presynaptic index -> global 512+j
#pragma unroll
            for (int r = 0; r < 3; r++)
                rec[r] += W[(size_t)(NIN + tid + r * 512) * NTOT + NIN + j];
        }
        if (tid == 0) cnt[cur ^ 1] = 0;
        __syncthreads();

#pragma unroll
        for (int r = 0; r < 3; r++) zc[r] = zn[r];
    }
}

// ---------------------------------------------------------------------------
extern "C" void kernel_launch(void* const* d_in, const int* in_sizes, int n_in,
                              void* d_out, int out_size) {
    const float* inp = (const float*)d_in[0];   // [64,512,512]
    const float* W   = (const float*)d_in[1];   // [2048,2048]
    float* out       = (float*)d_out;           // [64,256,512]

    transpose_w<<<(NIN * NEFF + 255) / 256, 256>>>(W);
    input_gemm<<<dim3(NEFF / 128, (NB * NT) / 128), 256>>>(inp);
    lif_kernel<<<NB, 512>>>(W, out);
}

// round 2
// speedup vs baseline: 2.3209x; 2.3209x over previous
#include <cuda_runtime.h>
#include <cuda_bf16.h>
#include <cstdint>
#include <cstddef>

// ---------------------------------------------------------------------------
// SpikeNN LIF. Neurons 0..511 are inert (outputs overwritten by input, not in
// the readout), so only neurons 512..2047 (NEFF=1536) are simulated.
//   Phase A: conv_w    : g_B[n][k]  = bf16(W[512+n][k]), k<512    (contig cast)
//            conv_inp  : g_A[b*512+t][k] = bf16(inp[b][k][t])     (transpose)
//   Phase B: tensor-core GEMM  Z[m][n] = sum_k A[m][k]*B[n][k]  (bf16->fp32)
//            Z stored bf16 (|Z|~0.02, threshold 1.0 -> spike-exact)
//   Phase C: sequential LIF, sparse recurrent spike gather (expected empty)
// ---------------------------------------------------------------------------

#define KOEFF 0.9512294245007140f   // exp(-1/20)
#define NEFF  1536
#define NIN   512
#define NTOT  2048
#define NB    64
#define NT    512
#define NOUT  256
#define MTOT  (NB * NT)             // 32768

__device__ __nv_bfloat16 g_Z[(size_t)MTOT * NEFF];   // 96 MB  [m][n]
__device__ __nv_bfloat16 g_A[(size_t)MTOT * NIN];    // 32 MB  [m][k]
__device__ __nv_bfloat16 g_B[(size_t)NEFF * NIN];    // 1.5 MB [n][k]

// ---------------------------------------------------------------------------
// PTX helpers
// ---------------------------------------------------------------------------
__device__ __forceinline__ uint32_t smem_u32(const void* p) {
    return (uint32_t)__cvta_generic_to_shared(p);
}
__device__ __forceinline__ void cp_async16(uint32_t dst, const void* src) {
    asm volatile("cp.async.cg.shared.global [%0], [%1], 16;\n" :: "r"(dst), "l"(src));
}
__device__ __forceinline__ void cp_commit() {
    asm volatile("cp.async.commit_group;\n");
}
template <int N>
__device__ __forceinline__ void cp_wait() {
    asm volatile("cp.async.wait_group %0;\n" :: "n"(N));
}
__device__ __forceinline__ void ldmatrix_x4(uint32_t* r, uint32_t addr) {
    asm volatile("ldmatrix.sync.aligned.m8n8.x4.shared.b16 {%0,%1,%2,%3}, [%4];\n"
                 : "=r"(r[0]), "=r"(r[1]), "=r"(r[2]), "=r"(r[3]) : "r"(addr));
}
__device__ __forceinline__ void mma_bf16(float* d, const uint32_t* a,
                                         uint32_t b0, uint32_t b1) {
    asm volatile(
        "mma.sync.aligned.m16n8k16.row.col.f32.bf16.bf16.f32 "
        "{%0,%1,%2,%3}, {%4,%5,%6,%7}, {%8,%9}, {%0,%1,%2,%3};\n"
        : "+f"(d[0]), "+f"(d[1]), "+f"(d[2]), "+f"(d[3])
        : "r"(a[0]), "r"(a[1]), "r"(a[2]), "r"(a[3]), "r"(b0), "r"(b1));
}

// ---------------------------------------------------------------------------
// conv_w: g_B[n][k] = bf16(W[(512+n)*2048 + k])   (k<512)
// ---------------------------------------------------------------------------
__global__ void conv_w(const float* __restrict__ W) {
    int idx = blockIdx.x * 256 + threadIdx.x;       // over NEFF*NIN/2
    if (idx < NEFF * NIN / 2) {
        int flat = idx * 2;
        int n = flat >> 9;
        int k = flat & 511;
        float2 v = *(const float2*)(W + (size_t)(NIN + n) * NTOT + k);
        *(__nv_bfloat162*)(g_B + (size_t)n * NIN + k) =
            __floats2bfloat162_rn(v.x, v.y);
    }
}

// ---------------------------------------------------------------------------
// conv_inp: g_A[b*512 + t][k] = bf16(inp[b][k][t])  -- 32x32 smem transpose
// ---------------------------------------------------------------------------
__global__ void conv_inp(const float* __restrict__ inp) {
    __shared__ float tile[32][33];
    const int b  = blockIdx.z;
    const int k0 = blockIdx.y * 32;
    const int t0 = blockIdx.x * 32;
    const int tx = threadIdx.x;      // 32
    const int ty = threadIdx.y;      // 8
    const float* src = inp + (size_t)b * (NIN * NT);
#pragma unroll
    for (int d = 0; d < 4; d++) {
        int k = ty * 4 + d;
        tile[k][tx] = src[(size_t)(k0 + k) * NT + t0 + tx];
    }
    __syncthreads();
#pragma unroll
    for (int d = 0; d < 4; d++) {
        int t = ty * 4 + d;
        g_A[(size_t)(b * NT + t0 + t) * NIN + k0 + tx] =
            __float2bfloat16(tile[tx][t]);
    }
}

// ---------------------------------------------------------------------------
// Tensor-core GEMM: Z[m][n] = sum_k A[m][k] * B[n][k]
// BM=BN=128, BK=32, 256 threads (8 warps as 4x2), warp tile 32x64,
// mma.m16n8k16 bf16, cp.async double buffer, smem row stride 40 bf16 (80B)
// -> ldmatrix 8-row phases hit banks {0,20,8,28,16,4,24,12}: conflict-free.
// ---------------------------------------------------------------------------
#define SSTR 40
__global__ void __launch_bounds__(256)
gemm_bf16(void) {
    __shared__ __align__(16) __nv_bfloat16 sA[2][128 * SSTR];
    __shared__ __align__(16) __nv_bfloat16 sB[2][128 * SSTR];

    const int blockN = blockIdx.x * 128;
    const int blockM = blockIdx.y * 128;
    const int tid  = threadIdx.x;
    const int warp = tid >> 5;
    const int lane = tid & 31;
    const int wm = (warp >> 1) * 32;
    const int wn = (warp & 1) * 64;

    const __nv_bfloat16* gA = g_A + (size_t)blockM * NIN;
    const __nv_bfloat16* gB = g_B + (size_t)blockN * NIN;

    // cp.async chunk assignment: 512 chunks of 16B per tile, 2 per thread
    const int c0row = tid >> 2,           c0kc = (tid & 3) * 8;
    const int c1row = (tid + 256) >> 2,   c1kc = (tid & 3) * 8;   // same kc

    uint32_t sAu[2] = { smem_u32(sA[0]), smem_u32(sA[1]) };
    uint32_t sBu[2] = { smem_u32(sB[0]), smem_u32(sB[1]) };

    // ldmatrix lane addressing
    const int lrow = (lane & 7) | (((lane >> 3) & 1) << 3);  // 0..15
    const int lkc  = (lane >> 4) * 8;                        // 0 or 8
    uint32_t aoff[2], boff[4];
#pragma unroll
    for (int i = 0; i < 2; i++)
        aoff[i] = ((wm + i * 16 + lrow) * SSTR + lkc) * 2;
#pragma unroll
    for (int j = 0; j < 4; j++)
        boff[j] = ((wn + j * 16 + lrow) * SSTR + lkc) * 2;

    float acc[2][8][4];
#pragma unroll
    for (int i = 0; i < 2; i++)
#pragma unroll
        for (int j = 0; j < 8; j++)
#pragma unroll
            for (int r = 0; r < 4; r++) acc[i][j][r] = 0.f;

    auto issue = [&](int s, int k0) {
        cp_async16(sAu[s] + (c0row * SSTR + c0kc) * 2,
                   gA + (size_t)c0row * NIN + k0 + c0kc);
        cp_async16(sAu[s] + (c1row * SSTR + c1kc) * 2,
                   gA + (size_t)c1row * NIN + k0 + c1kc);
        cp_async16(sBu[s] + (c0row * SSTR + c0kc) * 2,
                   gB + (size_t)c0row * NIN + k0 + c0kc);
        cp_async16(sBu[s] + (c1row * SSTR + c1kc) * 2,
                   gB + (size_t)c1row * NIN + k0 + c1kc);
        cp_commit();
    };

    const int NK = NIN / 32;    // 16
    issue(0, 0);

    for (int kt = 0; kt < NK; kt++) {
        const int s = kt & 1;
        if (kt + 1 < NK) { issue(s ^ 1, (kt + 1) * 32); cp_wait<1>(); }
        else             { cp_wait<0>(); }
        __syncthreads();

#pragma unroll
        for (int kc = 0; kc < 2; kc++) {
            const uint32_t koff = kc * 32;   // 16 bf16 = 32 bytes
            uint32_t af[2][4], bf[4][4];
#pragma unroll
            for (int i = 0; i < 2; i++)
                ldmatrix_x4(af[i], sAu[s] + aoff[i] + koff);
#pragma unroll
            for (int j = 0; j < 4; j++)
                ldmatrix_x4(bf[j], sBu[s] + boff[j] + koff);
#pragma unroll
            for (int i = 0; i < 2; i++)
#pragma unroll
                for (int j = 0; j < 4; j++) {
                    mma_bf16(acc[i][2 * j],     af[i], bf[j][0], bf[j][2]);
                    mma_bf16(acc[i][2 * j + 1], af[i], bf[j][1], bf[j][3]);
                }
        }
        __syncthreads();
    }

    // epilogue: bf16 stores (4B bf16x2 per fragment row pair)
    const int gid = lane >> 2;
    const int qid = lane & 3;
#pragma unroll
    for (int i = 0; i < 2; i++) {
        int row0 = blockM + wm + i * 16 + gid;
#pragma unroll
        for (int j = 0; j < 8; j++) {
            int col = blockN + wn + j * 8 + qid * 2;
            *(__nv_bfloat162*)(g_Z + (size_t)row0 * NEFF + col) =
                __floats2bfloat162_rn(acc[i][j][0], acc[i][j][1]);
            *(__nv_bfloat162*)(g_Z + (size_t)(row0 + 8) * NEFF + col) =
                __floats2bfloat162_rn(acc[i][j][2], acc[i][j][3]);
        }
    }
}

// ---------------------------------------------------------------------------
// Phase C: sequential LIF. One block per batch, 512 threads, 3 neurons/thread.
// ---------------------------------------------------------------------------
__global__ void __launch_bounds__(512)
lif_kernel(const float* __restrict__ W, float* __restrict__ out) {
    __shared__ int cnt[2];
    __shared__ int list[2][NEFF];

    const int b   = blockIdx.x;
    const int tid = threadIdx.x;

    float state[3] = {0.f, 0.f, 0.f};
    float refr[3]  = {0.f, 0.f, 0.f};
    float rec[3]   = {0.f, 0.f, 0.f};

    if (tid < 2) cnt[tid] = 0;

    const __nv_bfloat16* Zb = g_Z + (size_t)b * (NT * NEFF);
    float* outb = out + (size_t)b * (NOUT * NT);

    float zc[3], zn[3];
#pragma unroll
    for (int r = 0; r < 3; r++) zc[r] = __bfloat162float(Zb[tid + r * 512]);

    __syncthreads();

    for (int t = 0; t < NT; t++) {
        const int cur = t & 1;

        if (t < NT - 1) {
#pragma unroll
            for (int r = 0; r < 3; r++)
                zn[r] = __bfloat162float(Zb[(size_t)(t + 1) * NEFF + tid + r * 512]);
        }

        float sp2 = 0.f;
#pragma unroll
        for (int r = 0; r < 3; r++) {
            float s = state[r] * KOEFF + zc[r] + rec[r];
            if (refr[r] > 0.f) s = 0.f;
            bool spike = (s >= 1.f);
            refr[r] -= 1.f;
            if (spike) refr[r] = 2.f;
            if (s < -1.f) s = -1.f;
            state[r] = s;
            if (r == 2) sp2 = spike ? 1.f : 0.f;
            if (spike) {
                int p = atomicAdd(&cnt[cur], 1);
                list[cur][p] = tid + r * 512;
            }
        }

        if (tid >= 256) outb[(size_t)(tid - 256) * NT + t] = sp2;

        __syncthreads();

        const int n = cnt[cur];
        rec[0] = rec[1] = rec[2] = 0.f;
        for (int a = 0; a < n; a++) {
            int j = list[cur][a];
#pragma unroll
            for (int r = 0; r < 3; r++)
                rec[r] += W[(size_t)(NIN + tid + r * 512) * NTOT + NIN + j];
        }
        if (tid == 0) cnt[cur ^ 1] = 0;
        __syncthreads();

#pragma unroll
        for (int r = 0; r < 3; r++) zc[r] = zn[r];
    }
}

// ---------------------------------------------------------------------------
extern "C" void kernel_launch(void* const* d_in, const int* in_sizes, int n_in,
                              void* d_out, int out_size) {
    const float* inp = (const float*)d_in[0];   // [64,512,512]
    const float* W   = (const float*)d_in[1];   // [2048,2048]
    float* out       = (float*)d_out;           // [64,256,512]

    conv_w<<<(NEFF * NIN / 2 + 255) / 256, 256>>>(W);
    conv_inp<<<dim3(NT / 32, NIN / 32, NB), dim3(32, 8)>>>(inp);
    gemm_bf16<<<dim3(NEFF / 128, MTOT / 128), 256>>>();
    lif_kernel<<<NB, 512>>>(W, out);
}

// round 3
// speedup vs baseline: 4.9744x; 2.1433x over previous
#include <cuda_runtime.h>
#include <cuda_bf16.h>
#include <cstdint>
#include <cstddef>

// ---------------------------------------------------------------------------
// SpikeNN LIF. Neurons 0..511 are inert; simulate 512..2047 (NEFF=1536).
//   Phase A: conv_w  : g_B[n][k] = bf16(W[512+n][k]), zero per-batch flags
//            conv_inp: g_A[b*512+t][k] = bf16(inp[b][k][t])
//   Phase B: tensor-core GEMM  Z[m][n] = sum_k A[m][k]*B[n][k]  (bf16)
//   Phase C: lif_scan  — parallel per-neuron scan assuming no recurrent
//            spikes (exact until first spike); flags any spiking batch.
//            lif_fallback — exact sequential sim, runs only for flagged
//            batches (expected none), overwriting their output.
// ---------------------------------------------------------------------------

#define KOEFF 0.9512294245007140f   // exp(-1/20)
#define NEFF  1536
#define NIN   512
#define NTOT  2048
#define NB    64
#define NT    512
#define NOUT  256
#define MTOT  (NB * NT)             // 32768

__device__ __nv_bfloat16 g_Z[(size_t)MTOT * NEFF];   // 96 MB  [b][t][i]
__device__ __nv_bfloat16 g_A[(size_t)MTOT * NIN];    // 32 MB  [m][k]
__device__ __nv_bfloat16 g_B[(size_t)NEFF * NIN];    // 1.5 MB [n][k]
__device__ int g_flag[NB];

// ---------------------------------------------------------------------------
// PTX helpers
// ---------------------------------------------------------------------------
__device__ __forceinline__ uint32_t smem_u32(const void* p) {
    return (uint32_t)__cvta_generic_to_shared(p);
}
__device__ __forceinline__ void cp_async16(uint32_t dst, const void* src) {
    asm volatile("cp.async.cg.shared.global [%0], [%1], 16;\n" :: "r"(dst), "l"(src));
}
__device__ __forceinline__ void cp_commit() {
    asm volatile("cp.async.commit_group;\n");
}
template <int N>
__device__ __forceinline__ void cp_wait() {
    asm volatile("cp.async.wait_group %0;\n" :: "n"(N));
}
__device__ __forceinline__ void ldmatrix_x4(uint32_t* r, uint32_t addr) {
    asm volatile("ldmatrix.sync.aligned.m8n8.x4.shared.b16 {%0,%1,%2,%3}, [%4];\n"
                 : "=r"(r[0]), "=r"(r[1]), "=r"(r[2]), "=r"(r[3]) : "r"(addr));
}
__device__ __forceinline__ void mma_bf16(float* d, const uint32_t* a,
                                         uint32_t b0, uint32_t b1) {
    asm volatile(
        "mma.sync.aligned.m16n8k16.row.col.f32.bf16.bf16.f32 "
        "{%0,%1,%2,%3}, {%4,%5,%6,%7}, {%8,%9}, {%0,%1,%2,%3};\n"
        : "+f"(d[0]), "+f"(d[1]), "+f"(d[2]), "+f"(d[3])
        : "r"(a[0]), "r"(a[1]), "r"(a[2]), "r"(a[3]), "r"(b0), "r"(b1));
}

// ---------------------------------------------------------------------------
// conv_w: g_B[n][k] = bf16(W[(512+n)*2048 + k])   (k<512); also zero flags
// ---------------------------------------------------------------------------
__global__ void conv_w(const float* __restrict__ W) {
    int idx = blockIdx.x * 256 + threadIdx.x;       // over NEFF*NIN/2
    if (idx < NB) g_flag[idx] = 0;
    if (idx < NEFF * NIN / 2) {
        int flat = idx * 2;
        int n = flat >> 9;
        int k = flat & 511;
        float2 v = *(const float2*)(W + (size_t)(NIN + n) * NTOT + k);
        *(__nv_bfloat162*)(g_B + (size_t)n * NIN + k) =
            __floats2bfloat162_rn(v.x, v.y);
    }
}

// ---------------------------------------------------------------------------
// conv_inp: g_A[b*512 + t][k] = bf16(inp[b][k][t])  -- 32x32 smem transpose
// ---------------------------------------------------------------------------
__global__ void conv_inp(const float* __restrict__ inp) {
    __shared__ float tile[32][33];
    const int b  = blockIdx.z;
    const int k0 = blockIdx.y * 32;
    const int t0 = blockIdx.x * 32;
    const int tx = threadIdx.x;      // 32
    const int ty = threadIdx.y;      // 8
    const float* src = inp + (size_t)b * (NIN * NT);
#pragma unroll
    for (int d = 0; d < 4; d++) {
        int k = ty * 4 + d;
        tile[k][tx] = src[(size_t)(k0 + k) * NT + t0 + tx];
    }
    __syncthreads();
#pragma unroll
    for (int d = 0; d < 4; d++) {
        int t = ty * 4 + d;
        g_A[(size_t)(b * NT + t0 + t) * NIN + k0 + tx] =
            __float2bfloat16(tile[tx][t]);
    }
}

// ---------------------------------------------------------------------------
// Tensor-core GEMM: Z[m][n] = sum_k A[m][k] * B[n][k]
// BM=BN=128, BK=32, 256 threads (8 warps as 4x2), warp tile 32x64,
// mma.m16n8k16 bf16, cp.async double buffer, smem row stride 40 bf16.
// ---------------------------------------------------------------------------
#define SSTR 40
__global__ void __launch_bounds__(256)
gemm_bf16(void) {
    __shared__ __align__(16) __nv_bfloat16 sA[2][128 * SSTR];
    __shared__ __align__(16) __nv_bfloat16 sB[2][128 * SSTR];

    const int blockN = blockIdx.x * 128;
    const int blockM = blockIdx.y * 128;
    const int tid  = threadIdx.x;
    const int warp = tid >> 5;
    const int lane = tid & 31;
    const int wm = (warp >> 1) * 32;
    const int wn = (warp & 1) * 64;

    const __nv_bfloat16* gA = g_A + (size_t)blockM * NIN;
    const __nv_bfloat16* gB = g_B + (size_t)blockN * NIN;

    const int c0row = tid >> 2,           c0kc = (tid & 3) * 8;
    const int c1row = (tid + 256) >> 2,   c1kc = (tid & 3) * 8;

    uint32_t sAu[2] = { smem_u32(sA[0]), smem_u32(sA[1]) };
    uint32_t sBu[2] = { smem_u32(sB[0]), smem_u32(sB[1]) };

    const int lrow = (lane & 7) | (((lane >> 3) & 1) << 3);
    const int lkc  = (lane >> 4) * 8;
    uint32_t aoff[2], boff[4];
#pragma unroll
    for (int i = 0; i < 2; i++)
        aoff[i] = ((wm + i * 16 + lrow) * SSTR + lkc) * 2;
#pragma unroll
    for (int j = 0; j < 4; j++)
        boff[j] = ((wn + j * 16 + lrow) * SSTR + lkc) * 2;

    float acc[2][8][4];
#pragma unroll
    for (int i = 0; i < 2; i++)
#pragma unroll
        for (int j = 0; j < 8; j++)
#pragma unroll
            for (int r = 0; r < 4; r++) acc[i][j][r] = 0.f;

    auto issue = [&](int s, int k0) {
        cp_async16(sAu[s] + (c0row * SSTR + c0kc) * 2,
                   gA + (size_t)c0row * NIN + k0 + c0kc);
        cp_async16(sAu[s] + (c1row * SSTR + c1kc) * 2,
                   gA + (size_t)c1row * NIN + k0 + c1kc);
        cp_async16(sBu[s] + (c0row * SSTR + c0kc) * 2,
                   gB + (size_t)c0row * NIN + k0 + c0kc);
        cp_async16(sBu[s] + (c1row * SSTR + c1kc) * 2,
                   gB + (size_t)c1row * NIN + k0 + c1kc);
        cp_commit();
    };

    const int NK = NIN / 32;    // 16
    issue(0, 0);

    for (int kt = 0; kt < NK; kt++) {
        const int s = kt & 1;
        if (kt + 1 < NK) { issue(s ^ 1, (kt + 1) * 32); cp_wait<1>(); }
        else             { cp_wait<0>(); }
        __syncthreads();

#pragma unroll
        for (int kc = 0; kc < 2; kc++) {
            const uint32_t koff = kc * 32;
            uint32_t af[2][4], bf[4][4];
#pragma unroll
            for (int i = 0; i < 2; i++)
                ldmatrix_x4(af[i], sAu[s] + aoff[i] + koff);
#pragma unroll
            for (int j = 0; j < 4; j++)
                ldmatrix_x4(bf[j], sBu[s] + boff[j] + koff);
#pragma unroll
            for (int i = 0; i < 2; i++)
#pragma unroll
                for (int j = 0; j < 4; j++) {
                    mma_bf16(acc[i][2 * j],     af[i], bf[j][0], bf[j][2]);
                    mma_bf16(acc[i][2 * j + 1], af[i], bf[j][1], bf[j][3]);
                }
        }
        __syncthreads();
    }

    const int gid = lane >> 2;
    const int qid = lane & 3;
#pragma unroll
    for (int i = 0; i < 2; i++) {
        int row0 = blockM + wm + i * 16 + gid;
#pragma unroll
        for (int j = 0; j < 8; j++) {
            int col = blockN + wn + j * 8 + qid * 2;
            *(__nv_bfloat162*)(g_Z + (size_t)row0 * NEFF + col) =
                __floats2bfloat162_rn(acc[i][j][0], acc[i][j][1]);
            *(__nv_bfloat162*)(g_Z + (size_t)(row0 + 8) * NEFF + col) =
                __floats2bfloat162_rn(acc[i][j][2], acc[i][j][3]);
        }
    }
}

// ---------------------------------------------------------------------------
// lif_scan: one thread per (batch, neuron). Exact dynamics under the
// "no recurrent spikes" assumption; raises g_flag[b] if any spike fires.
// Pre-first-spike the trajectory is exact (refractory never engaged, rec=0).
// 3 blocks of 512 threads per batch -> 192 blocks.
// ---------------------------------------------------------------------------
__global__ void __launch_bounds__(512)
lif_scan(float* __restrict__ out) {
    const int b = blockIdx.x / 3;
    const int i = (blockIdx.x % 3) * 512 + threadIdx.x;   // local neuron

    const __nv_bfloat16* Zp = g_Z + (size_t)b * NT * NEFF + i;
    const bool is_out = (i >= NEFF - NOUT);
    float* orow = out + ((size_t)b * NOUT + (i - (NEFF - NOUT))) * NT;

    float state = 0.f;
    bool any = false;

    for (int t0 = 0; t0 < NT; t0 += 8) {
        float z[8];
#pragma unroll
        for (int u = 0; u < 8; u++)
            z[u] = __bfloat162float(Zp[(size_t)(t0 + u) * NEFF]);
        float sp[8];
#pragma unroll
        for (int u = 0; u < 8; u++) {
            float s = state * KOEFF + z[u];
            bool spike = (s >= 1.f);
            any |= spike;
            if (s < -1.f) s = -1.f;
            state = s;
            sp[u] = spike ? 1.f : 0.f;
        }
        if (is_out) {
            *(float4*)(orow + t0)     = make_float4(sp[0], sp[1], sp[2], sp[3]);
            *(float4*)(orow + t0 + 4) = make_float4(sp[4], sp[5], sp[6], sp[7]);
        }
    }
    if (any) g_flag[b] = 1;
}

// ---------------------------------------------------------------------------
// lif_fallback: exact sequential sim (recurrence + refractory). Runs only for
// batches where lif_scan saw a spike; otherwise returns immediately.
// ---------------------------------------------------------------------------
__global__ void __launch_bounds__(512)
lif_fallback(const float* __restrict__ W, float* __restrict__ out) {
    const int b = blockIdx.x;
    if (g_flag[b] == 0) return;

    __shared__ int cnt[2];
    __shared__ int list[2][NEFF];

    const int tid = threadIdx.x;

    float state[3] = {0.f, 0.f, 0.f};
    float refr[3]  = {0.f, 0.f, 0.f};
    float rec[3]   = {0.f, 0.f, 0.f};

    if (tid < 2) cnt[tid] = 0;

    const __nv_bfloat16* Zb = g_Z + (size_t)b * (NT * NEFF);
    float* outb = out + (size_t)b * (NOUT * NT);

    float zc[3], zn[3];
#pragma unroll
    for (int r = 0; r < 3; r++) zc[r] = __bfloat162float(Zb[tid + r * 512]);

    __syncthreads();

    for (int t = 0; t < NT; t++) {
        const int cur = t & 1;

        if (t < NT - 1) {
#pragma unroll
            for (int r = 0; r < 3; r++)
                zn[r] = __bfloat162float(Zb[(size_t)(t + 1) * NEFF + tid + r * 512]);
        }

        float sp2 = 0.f;
#pragma unroll
        for (int r = 0; r < 3; r++) {
            float s = state[r] * KOEFF + zc[r] + rec[r];
            if (refr[r] > 0.f) s = 0.f;
            bool spike = (s >= 1.f);
            refr[r] -= 1.f;
            if (spike) refr[r] = 2.f;
            if (s < -1.f) s = -1.f;
            state[r] = s;
            if (r == 2) sp2 = spike ? 1.f : 0.f;
            if (spike) {
                int p = atomicAdd(&cnt[cur], 1);
                list[cur][p] = tid + r * 512;
            }
        }

        if (tid >= 256) outb[(size_t)(tid - 256) * NT + t] = sp2;

        __syncthreads();

        const int n = cnt[cur];
        rec[0] = rec[1] = rec[2] = 0.f;
        for (int a = 0; a < n; a++) {
            int j = list[cur][a];
#pragma unroll
            for (int r = 0; r < 3; r++)
                rec[r] += W[(size_t)(NIN + tid + r * 512) * NTOT + NIN + j];
        }
        if (tid == 0) cnt[cur ^ 1] = 0;
        __syncthreads();

#pragma unroll
        for (int r = 0; r < 3; r++) zc[r] = zn[r];
    }
}

// ---------------------------------------------------------------------------
extern "C" void kernel_launch(void* const* d_in, const int* in_sizes, int n_in,
                              void* d_out, int out_size) {
    const float* inp = (const float*)d_in[0];   // [64,512,512]
    const float* W   = (const float*)d_in[1];   // [2048,2048]
    float* out       = (float*)d_out;           // [64,256,512]

    conv_w<<<(NEFF * NIN / 2 + 255) / 256, 256>>>(W);
    conv_inp<<<dim3(NT / 32, NIN / 32, NB), dim3(32, 8)>>>(inp);
    gemm_bf16<<<dim3(NEFF / 128, MTOT / 128), 256>>>();
    lif_scan<<<NB * 3, 512>>>(out);
    lif_fallback<<<NB, 512>>>(W, out);
}

// round 5
// speedup vs baseline: 5.4030x; 1.0862x over previous
#include <cuda_runtime.h>
#include <cuda_bf16.h>
#include <cuda_fp8.h>
#include <cstdint>
#include <cstddef>

// ---------------------------------------------------------------------------
// SpikeNN LIF. Neurons 0..511 inert; simulate 512..2047 (NEFF=1536).
//   conv_w  : g_B[n][k] = e4m3(W[512+n][k] * 256)   (k<512); zero flags
//   conv_inp: g_A[b*512+t][k] = e4m3(inp[b][k][t])  (binary -> 0x38/0x00)
//   gemm_fp8: Zs[b][i][t] = e4m3( sum_k A*B )  == 256*Z, mma.sync e4m3,
//             fp32 accum, smem-transposed epilogue -> [b][i][t] layout
//   lif_scan: per-neuron scan (256-scaled state), exact until first spike,
//             flags spiking batches
//   lif_fallback: exact sequential sim for flagged batches (expected none)
// ---------------------------------------------------------------------------

#define KOEFF 0.9512294245007140f   // exp(-1/20)
#define NEFF  1536
#define NIN   512
#define NTOT  2048
#define NB    64
#define NT    512
#define NOUT  256
#define MTOT  (NB * NT)             // 32768

__device__ uint8_t g_Z[(size_t)NB * NEFF * NT];   // 48 MB  [b][i][t]  (e4m3 of 256*Z)
__device__ uint8_t g_A[(size_t)MTOT * NIN];       // 16 MB  [m][k]
__device__ uint8_t g_B[(size_t)NEFF * NIN];       // 0.75MB [n][k]
__device__ int g_flag[NB];

// ---------------------------------------------------------------------------
// helpers
// ---------------------------------------------------------------------------
__device__ __forceinline__ uint32_t smem_u32(const void* p) {
    return (uint32_t)__cvta_generic_to_shared(p);
}
__device__ __forceinline__ void cp_async16(uint32_t dst, const void* src) {
    asm volatile("cp.async.cg.shared.global [%0], [%1], 16;\n" :: "r"(dst), "l"(src));
}
__device__ __forceinline__ void cp_commit() {
    asm volatile("cp.async.commit_group;\n");
}
template <int N>
__device__ __forceinline__ void cp_wait() {
    asm volatile("cp.async.wait_group %0;\n" :: "n"(N));
}
__device__ __forceinline__ void ldmatrix_x4(uint32_t* r, uint32_t addr) {
    asm volatile("ldmatrix.sync.aligned.m8n8.x4.shared.b16 {%0,%1,%2,%3}, [%4];\n"
                 : "=r"(r[0]), "=r"(r[1]), "=r"(r[2]), "=r"(r[3]) : "r"(addr));
}
// fp8 e4m3 MMA: fragment byte-layout == bf16 m16n8k16 fragments
__device__ __forceinline__ void mma_fp8(float* d, const uint32_t* a,
                                        uint32_t b0, uint32_t b1) {
    asm volatile(
        "mma.sync.aligned.m16n8k32.row.col.f32.e4m3.e4m3.f32 "
        "{%0,%1,%2,%3}, {%4,%5,%6,%7}, {%8,%9}, {%0,%1,%2,%3};\n"
        : "+f"(d[0]), "+f"(d[1]), "+f"(d[2]), "+f"(d[3])
        : "r"(a[0]), "r"(a[1]), "r"(a[2]), "r"(a[3]), "r"(b0), "r"(b1));
}
__device__ __forceinline__ float dec_fp8(uint8_t v) {
    __half_raw h = __nv_cvt_fp8_to_halfraw((__nv_fp8_storage_t)v, __NV_E4M3);
    return __half2float(*(__half*)&h);
}
__device__ __forceinline__ void dec_fp8x4(uint32_t w, float* f) {
    __half2_raw h01 = __nv_cvt_fp8x2_to_halfraw2((__nv_fp8x2_storage_t)(w & 0xFFFF), __NV_E4M3);
    __half2_raw h23 = __nv_cvt_fp8x2_to_halfraw2((__nv_fp8x2_storage_t)(w >> 16),    __NV_E4M3);
    float2 a = __half22float2(*(__half2*)&h01);
    float2 b = __half22float2(*(__half2*)&h23);
    f[0] = a.x; f[1] = a.y; f[2] = b.x; f[3] = b.y;
}

// ---------------------------------------------------------------------------
// conv_w: g_B[n][k] = e4m3(W[(512+n)*2048 + k] * 256); zero flags
// ---------------------------------------------------------------------------
__global__ void conv_w(const float* __restrict__ W) {
    int idx = blockIdx.x * 256 + threadIdx.x;
    if (idx < NB) g_flag[idx] = 0;
    if (idx < NEFF * NIN / 2) {
        int flat = idx * 2;
        int n = flat >> 9;
        int k = flat & 511;
        float2 v = *(const float2*)(W + (size_t)(NIN + n) * NTOT + k);
        __nv_fp8x2_storage_t p = __nv_cvt_float2_to_fp8x2(
            make_float2(v.x * 256.f, v.y * 256.f), __NV_SATFINITE, __NV_E4M3);
        *(uint16_t*)(g_B + (size_t)n * NIN + k) = (uint16_t)p;
    }
}

// ---------------------------------------------------------------------------
// conv_inp: g_A[b*512 + t][k] = binary fp8 (1.0 = 0x38)
// ---------------------------------------------------------------------------
__global__ void conv_inp(const float* __restrict__ inp) {
    __shared__ float tile[32][33];
    const int b  = blockIdx.z;
    const int k0 = blockIdx.y * 32;
    const int t0 = blockIdx.x * 32;
    const int tx = threadIdx.x;      // 32
    const int ty = threadIdx.y;      // 8
    const float* src = inp + (size_t)b * (NIN * NT);
#pragma unroll
    for (int d = 0; d < 4; d++) {
        int k = ty * 4 + d;
        tile[k][tx] = src[(size_t)(k0 + k) * NT + t0 + tx];
    }
    __syncthreads();
#pragma unroll
    for (int d = 0; d < 4; d++) {
        int t = ty * 4 + d;
        g_A[(size_t)(b * NT + t0 + t) * NIN + k0 + tx] =
            (tile[tx][t] != 0.f) ? 0x38 : 0x00;
    }
}

// ---------------------------------------------------------------------------
// gemm_fp8: 256*Z[m][n] = sum_k A[m][k]*B[n][k], e4m3 inputs, fp32 accum.
// BM=BN=128, BK=64 bytes, 256 threads (8 warps 4x2), warp tile 32x64,
// mma.m16n8k32, cp.async double buffer, smem row stride 80B (ldmatrix
// conflict-free). Epilogue: fp8 quantize -> smem transpose -> Z[b][i][t].
// ---------------------------------------------------------------------------
#define SSTR 80
#define TSTR 144
__global__ void __launch_bounds__(256)
gemm_fp8(void) {
    __shared__ __align__(16) uint8_t smem_all[4 * 128 * SSTR];   // 40960 B
    uint8_t* tbuf = smem_all;                                     // epilogue alias

    const uint32_t sA0 = smem_u32(smem_all);
    const uint32_t sA1 = sA0 + 128 * SSTR;
    const uint32_t sB0 = sA1 + 128 * SSTR;
    const uint32_t sB1 = sB0 + 128 * SSTR;
    const uint32_t sAu[2] = { sA0, sA1 };
    const uint32_t sBu[2] = { sB0, sB1 };

    const int blockN = blockIdx.x * 128;
    const int blockM = blockIdx.y * 128;
    const int b      = blockM >> 9;
    const int tbase  = blockM & 511;

    const int tid  = threadIdx.x;
    const int warp = tid >> 5;
    const int lane = tid & 31;
    const int wm = (warp >> 1) * 32;
    const int wn = (warp & 1) * 64;

    const uint8_t* gA = g_A + (size_t)blockM * NIN;
    const uint8_t* gB = g_B + (size_t)blockN * NIN;

    const int crow = tid >> 2;              // 0..63
    const int ccol = (tid & 3) * 16;        // 0,16,32,48

    const int lrow = (lane & 7) | (((lane >> 3) & 1) << 3);
    const int lkc  = (lane >> 4) * 16;
    uint32_t aoff[2], boff[4];
#pragma unroll
    for (int i = 0; i < 2; i++)
        aoff[i] = (uint32_t)((wm + i * 16 + lrow) * SSTR + lkc);
#pragma unroll
    for (int j = 0; j < 4; j++)
        boff[j] = (uint32_t)((wn + j * 16 + lrow) * SSTR + lkc);

    float acc[2][8][4];
#pragma unroll
    for (int i = 0; i < 2; i++)
#pragma unroll
        for (int j = 0; j < 8; j++)
#pragma unroll
            for (int r = 0; r < 4; r++) acc[i][j][r] = 0.f;

    auto issue = [&](int s, int k0) {
        cp_async16(sAu[s] + crow * SSTR + ccol,
                   gA + (size_t)crow * NIN + k0 + ccol);
        cp_async16(sAu[s] + (crow + 64) * SSTR + ccol,
                   gA + (size_t)(crow + 64) * NIN + k0 + ccol);
        cp_async16(sBu[s] + crow * SSTR + ccol,
                   gB + (size_t)crow * NIN + k0 + ccol);
        cp_async16(sBu[s] + (crow + 64) * SSTR + ccol,
                   gB + (size_t)(crow + 64) * NIN + k0 + ccol);
        cp_commit();
    };

    const int NK = NIN / 64;    // 8
    issue(0, 0);

    for (int kt = 0; kt < NK; kt++) {
        const int s = kt & 1;
        if (kt + 1 < NK) { issue(s ^ 1, (kt + 1) * 64); cp_wait<1>(); }
        else             { cp_wait<0>(); }
        __syncthreads();

#pragma unroll
        for (int kc = 0; kc < 2; kc++) {
            const uint32_t koff = kc * 32;   // 32 fp8 = 32 bytes = k32
            uint32_t af[2][4], bf[4][4];
#pragma unroll
            for (int i = 0; i < 2; i++)
                ldmatrix_x4(af[i], sAu[s] + aoff[i] + koff);
#pragma unroll
            for (int j = 0; j < 4; j++)
                ldmatrix_x4(bf[j], sBu[s] + boff[j] + koff);
#pragma unroll
            for (int i = 0; i < 2; i++)
#pragma unroll
                for (int j = 0; j < 4; j++) {
                    mma_fp8(acc[i][2 * j],     af[i], bf[j][0], bf[j][2]);
                    mma_fp8(acc[i][2 * j + 1], af[i], bf[j][1], bf[j][3]);
                }
        }
        __syncthreads();
    }

    // ---- epilogue: quantize to e4m3, transpose via smem, store [b][i][t] ----
    const int gid = lane >> 2;
    const int qid = lane & 3;
#pragma unroll
    for (int i = 0; i < 2; i++) {
        int t1 = wm + i * 16 + gid;
        int t2 = t1 + 8;
#pragma unroll
        for (int j = 0; j < 8; j++) {
            int n = wn + j * 8 + qid * 2;
            tbuf[(n)     * TSTR + t1] = (uint8_t)__nv_cvt_float_to_fp8(acc[i][j][0], __NV_SATFINITE, __NV_E4M3);
            tbuf[(n + 1) * TSTR + t1] = (uint8_t)__nv_cvt_float_to_fp8(acc[i][j][1], __NV_SATFINITE, __NV_E4M3);
            tbuf[(n)     * TSTR + t2] = (uint8_t)__nv_cvt_float_to_fp8(acc[i][j][2], __NV_SATFINITE, __NV_E4M3);
            tbuf[(n + 1) * TSTR + t2] = (uint8_t)__nv_cvt_float_to_fp8(acc[i][j][3], __NV_SATFINITE, __NV_E4M3);
        }
    }
    __syncthreads();

#pragma unroll
    for (int r = 0; r < 4; r++) {
        int idx = tid * 4 + r;          // 0..1023
        int n = idx >> 3;               // 0..127
        int c = idx & 7;                // 0..7 (16 t each)
        uint4 v = *(const uint4*)(tbuf + n * TSTR + c * 16);
        *(uint4*)(g_Z + ((size_t)(b * NEFF + blockN + n)) * NT + tbase + c * 16) = v;
    }
}

// ---------------------------------------------------------------------------
// lif_scan: one thread per (batch, neuron), state kept 256-scaled.
// Exact until the batch's first spike; flags such batches for fallback.
// ---------------------------------------------------------------------------
__global__ void __launch_bounds__(256)
lif_scan(float* __restrict__ out) {
    const int b = blockIdx.x / 6;
    const int i = (blockIdx.x % 6) * 256 + threadIdx.x;

    const uint8_t* Zr = g_Z + ((size_t)b * NEFF + i) * NT;
    const bool is_out = (i >= NEFF - NOUT);
    float* orow = out + ((size_t)b * NOUT + (i - (NEFF - NOUT))) * NT;

    float state = 0.f;          // 256-scaled
    bool any = false;

    for (int t0 = 0; t0 < NT; t0 += 16) {
        uint4 v = *(const uint4*)(Zr + t0);
        float z[16];
        dec_fp8x4(v.x, z);
        dec_fp8x4(v.y, z + 4);
        dec_fp8x4(v.z, z + 8);
        dec_fp8x4(v.w, z + 12);
        float sp[16];
#pragma unroll
        for (int u = 0; u < 16; u++) {
            float s = fmaf(state, KOEFF, z[u]);
            bool spike = (s >= 256.f);
            any |= spike;
            state = (s < -256.f) ? -256.f : s;
            sp[u] = spike ? 1.f : 0.f;
        }
        if (is_out) {
#pragma unroll
            for (int q = 0; q < 4; q++)
                *(float4*)(orow + t0 + q * 4) =
                    make_float4(sp[4 * q], sp[4 * q + 1], sp[4 * q + 2], sp[4 * q + 3]);
        }
    }
    if (any) g_flag[b] = 1;
}

// ---------------------------------------------------------------------------
// lif_fallback: exact sequential sim (recurrence + refractory), 256-scaled.
// Runs only for flagged batches (expected none).
// ---------------------------------------------------------------------------
__global__ void __launch_bounds__(512)
lif_fallback(const float* __restrict__ W, float* __restrict__ out) {
    const int b = blockIdx.x;
    if (g_flag[b] == 0) return;

    __shared__ int cnt[2];
    __shared__ int list[2][NEFF];

    const int tid = threadIdx.x;

    float state[3] = {0.f, 0.f, 0.f};
    float refr[3]  = {0.f, 0.f, 0.f};
    float rec[3]   = {0.f, 0.f, 0.f};

    if (tid < 2) cnt[tid] = 0;

    const uint8_t* Zb = g_Z + (size_t)b * NEFF * NT;   // [i][t]
    float* outb = out + (size_t)b * (NOUT * NT);

    __syncthreads();

    for (int t = 0; t < NT; t++) {
        const int cur = t & 1;

        float sp2 = 0.f;
#pragma unroll
        for (int r = 0; r < 3; r++) {
            float z = dec_fp8(Zb[(size_t)(tid + r * 512) * NT + t]);   // 256-scaled
            float s = state[r] * KOEFF + z + rec[r] * 256.f;
            if (refr[r] > 0.f) s = 0.f;
            bool spike = (s >= 256.f);
            refr[r] -= 1.f;
            if (spike) refr[r] = 2.f;
            if (s < -256.f) s = -256.f;
            state[r] = s;
            if (r == 2) sp2 = spike ? 1.f : 0.f;
            if (spike) {
                int pslot = atomicAdd(&cnt[cur], 1);
                list[cur][pslot] = tid + r * 512;
            }
        }

        if (tid >= 256) outb[(size_t)(tid - 256) * NT + t] = sp2;

        __syncthreads();

        const int n = cnt[cur];
        rec[0] = rec[1] = rec[2] = 0.f;
        for (int a = 0; a < n; a++) {
            int j = list[cur][a];
#pragma unroll
            for (int r = 0; r < 3; r++)
                rec[r] += W[(size_t)(NIN + tid + r * 512) * NTOT + NIN + j];
        }
        if (tid == 0) cnt[cur ^ 1] = 0;
        __syncthreads();
    }
}

// ---------------------------------------------------------------------------
extern "C" void kernel_launch(void* const* d_in, const int* in_sizes, int n_in,
                              void* d_out, int out_size) {
    const float* inp = (const float*)d_in[0];   // [64,512,512]
    const float* W   = (const float*)d_in[1];   // [2048,2048]
    float* out       = (float*)d_out;           // [64,256,512]

    conv_w<<<(NEFF * NIN / 2 + 255) / 256, 256>>>(W);
    conv_inp<<<dim3(NT / 32, NIN / 32, NB), dim3(32, 8)>>>(inp);
    gemm_fp8<<<dim3(NEFF / 128, MTOT / 128), 256>>>();
    lif_scan<<<NB * 6, 256>>>(out);
    lif_fallback<<<NB, 512>>>(W, out);
}